// round 11
// baseline (speedup 1.0000x reference)
#include <cuda_runtime.h>
#include <cuda_fp16.h>
#include <cstdint>

// ---------------------------------------------------------------------------
// TFN forward. R11: tcgen05 unavailable (harness lowers via .target sm_103,
// no 'a' suffix -> ptxas rejects tcgen05). Back to R9 structure with warp
// grid changed 4m x 2n -> 2m x 4n: each warp covers 32 m-rows x 24 n-cols,
// so the B tile is LDSM-read 2x instead of 4x (86KB -> 43KB smem traffic
// per chunk). Prefetch-distance-3 ring and enc/tail unchanged from R9.
// ---------------------------------------------------------------------------

#define NBLK   152
#define BDIM   64
#define HDIM   96
#define LDH    104            // smem B row stride in halfs (208 B, LDSM conflict-free)
#define KROWS  112            // 97 data rows + 15 zero pad (7 k16 steps)
#define WBUFH  (KROWS * LDH)  // halfs per stage buffer
#define SMEM_BYTES (3*WBUFH*2 + 2*6208*4)

__device__ float g_a1[BDIM * 97];
__device__ float g_v1[BDIM * 97];
__device__ float g_t1[BDIM * 97];
__device__ float g_part[NBLK * BDIM * HDIM];

// ---------------------------------------------------------------------------

__device__ __forceinline__ uint32_t h2u(__half2 h) {
    return *reinterpret_cast<uint32_t*>(&h);
}

__device__ __forceinline__ void mma_f16(float c[4],
                                        uint32_t a0, uint32_t a1,
                                        uint32_t a2, uint32_t a3,
                                        uint32_t b0, uint32_t b1) {
    asm volatile(
        "mma.sync.aligned.m16n8k16.row.col.f32.f16.f16.f32 "
        "{%0,%1,%2,%3}, {%4,%5,%6,%7}, {%8,%9}, {%0,%1,%2,%3};"
        : "+f"(c[0]), "+f"(c[1]), "+f"(c[2]), "+f"(c[3])
        : "r"(a0), "r"(a1), "r"(a2), "r"(a3), "r"(b0), "r"(b1));
}

struct __align__(8) H4 { __half2 a, b; };

// 97*96 = 9312 floats = 2328 float4 per chunk. 256 threads: 9 each + 24 extra.
__device__ __forceinline__ void stage_ldg(float4 (&stg)[10],
                                          const float* __restrict__ W1,
                                          int av, int tid) {
    const float4* src = reinterpret_cast<const float4*>(W1 + (size_t)av * 9312);
#pragma unroll
    for (int j = 0; j < 9; j++) stg[j] = src[tid + j * 256];
    if (tid < 24) stg[9] = src[2304 + tid];
}

__device__ __forceinline__ void cvt_store(__half* buf, int q, float4 v) {
    int e = q * 4;
    int t = e / 96;
    int c = e - t * 96;
    H4 o;
    o.a = __floats2half2_rn(v.x, v.y);
    o.b = __floats2half2_rn(v.z, v.w);
    *reinterpret_cast<H4*>(buf + t * LDH + c) = o;
}

__device__ __forceinline__ void stage_sts(__half* buf, const float4 (&stg)[10],
                                          int tid) {
#pragma unroll
    for (int j = 0; j < 9; j++) cvt_store(buf, tid + j * 256, stg[j]);
    if (tid < 24) cvt_store(buf, 2304 + tid, stg[9]);
}

// ---------------------------------------------------------------------------
// Kernel 1: encoders. grid (64 batch, 3 mods), 768 threads = 96 h x 8 slices.
// ---------------------------------------------------------------------------
__global__ void __launch_bounds__(768) tfn_enc(
    const float* __restrict__ audios, const float* __restrict__ texts,
    const float* __restrict__ videos,
    const float* __restrict__ Wa, const float* __restrict__ ba,
    const float* __restrict__ Wt, const float* __restrict__ bt,
    const float* __restrict__ Wv, const float* __restrict__ bv) {
    const int b   = blockIdx.x;
    const int mod = blockIdx.y;
    const int tid = threadIdx.x;

    const float* x; const float* W; const float* bias; float* out; int K;
    if (mod == 0)      { x = audios; W = Wa; bias = ba; out = g_a1; K = 512; }
    else if (mod == 1) { x = texts;  W = Wt; bias = bt; out = g_t1; K = 1024; }
    else               { x = videos; W = Wv; bias = bv; out = g_v1; K = 512; }

    __shared__ float xs[1024];
    __shared__ float ps[768];

    const float* xb = x + (size_t)b * K;
    for (int i = tid; i < K; i += 768) xs[i] = xb[i];
    __syncthreads();

    const int h  = tid % 96;
    const int g  = tid / 96;           // 0..7
    const int kq = K >> 3;             // 64 or 128
    const int k0 = g * kq;

    float acc = 0.f;
#pragma unroll 8
    for (int k = k0; k < k0 + kq; k++)
        acc += xs[k] * W[k * HDIM + h];
    ps[tid] = acc;
    __syncthreads();

    if (g == 0) {
        float r = bias[h];
#pragma unroll
        for (int i = 0; i < 8; i++) r += ps[h + 96 * i];
        out[b * 97 + 1 + h] = fmaxf(r, 0.f);
        if (h == 0) out[b * 97] = 1.f;
    }
}

// ---------------------------------------------------------------------------
// Kernel 2: main fused trilinear GEMM (y1 partials, pre-bias/relu)
//   152 CTAs x 256 threads, 1 CTA/SM, prefetch distance 3, warp grid 2m x 4n
// ---------------------------------------------------------------------------
__global__ void __launch_bounds__(256, 1) tfn_main(const float* __restrict__ W1) {
    extern __shared__ char smx[];
    __half* wb0 = reinterpret_cast<__half*>(smx);
    __half* wb1 = wb0 + WBUFH;
    __half* wb2 = wb1 + WBUFH;
    float*  a1s = reinterpret_cast<float*>(wb2 + WBUFH);
    float*  v1s = a1s + 6208;

    const int tid  = threadIdx.x;
    const int lane = tid & 31;
    const int wid  = tid >> 5;
    const int wm   = wid & 1;    // m-warp: batch rows 32*wm..32*wm+31 (2 tiles)
    const int wn   = wid >> 1;   // n-warp: cols 24*wn..24*wn+23
    const int gid  = lane >> 2;
    const int tig  = lane & 3;
    const int b0   = wm * 32 + gid;      // tile0 rows b0, b0+8
    const int b1r  = b0 + 16;            // tile1 rows b1r, b1r+8
    const int nbase = wn * 24;

    for (int i = tid; i < 6208; i += 256) { a1s[i] = g_a1[i]; v1s[i] = g_v1[i]; }
    // zero pad rows 97..111 of all three buffers (780 u32 each)
    for (int i = tid; i < 3 * 780; i += 256) {
        int s = i / 780, r = i - s * 780;
        reinterpret_cast<uint32_t*>(wb0 + s * WBUFH + 97 * LDH)[r] = 0;
    }

    // persistent t1 A-fragments as half2 pairs, two m-tiles: 7 k16-steps
    __half2 t1f[7][4], t1g[7][4];
#pragma unroll
    for (int ks = 0; ks < 7; ks++) {
        int ka = ks * 16 + 2 * tig;
        int kb = ka + 8;
#pragma unroll
        for (int mt = 0; mt < 2; mt++) {
            int r0 = (mt ? b1r : b0);
            float x0 = (ka     < 97) ? g_t1[r0 * 97 + ka]           : 0.f;
            float x1 = (ka + 1 < 97) ? g_t1[r0 * 97 + ka + 1]       : 0.f;
            float y0 = (ka     < 97) ? g_t1[(r0 + 8) * 97 + ka]     : 0.f;
            float y1 = (ka + 1 < 97) ? g_t1[(r0 + 8) * 97 + ka + 1] : 0.f;
            float x2 = (kb     < 97) ? g_t1[r0 * 97 + kb]           : 0.f;
            float x3 = (kb + 1 < 97) ? g_t1[r0 * 97 + kb + 1]       : 0.f;
            float y2 = (kb     < 97) ? g_t1[(r0 + 8) * 97 + kb]     : 0.f;
            float y3 = (kb + 1 < 97) ? g_t1[(r0 + 8) * 97 + kb + 1] : 0.f;
            __half2 (&tf)[4] = mt ? t1g[ks] : t1f[ks];
            tf[0] = __floats2half2_rn(x0, x1);
            tf[1] = __floats2half2_rn(y0, y1);
            tf[2] = __floats2half2_rn(x2, x3);
            tf[3] = __floats2half2_rn(y2, y3);
        }
    }

    // Y[0..2] = tile0 n8-blocks, Y[3..5] = tile1 n8-blocks
    float Y[6][4];
#pragma unroll
    for (int j = 0; j < 6; j++) { Y[j][0] = Y[j][1] = Y[j][2] = Y[j][3] = 0.f; }

    const int bk = blockIdx.x;
    // 9409 = 152*61 + 137 : first 137 blocks take 62 chunks
    const int cstart = (bk < 137) ? bk * 62 : bk * 61 + 137;
    const int ccnt   = (bk < 137) ? 62 : 61;

    const int lrow = lane & 15;          // k row within k16 step
    const int lcol = (lane >> 4) * 8;    // 0 or 8 within n16 block

    auto compute = [&](int av, const __half* curb) {
        const int ca = av / 97;
        const int cv = av - ca * 97;
        const __half2 m0h = __float2half2_rn(a1s[b0 * 97 + ca] * v1s[b0 * 97 + cv]);
        const __half2 m1h = __float2half2_rn(a1s[(b0 + 8) * 97 + ca] * v1s[(b0 + 8) * 97 + cv]);
        const __half2 m2h = __float2half2_rn(a1s[b1r * 97 + ca] * v1s[b1r * 97 + cv]);
        const __half2 m3h = __float2half2_rn(a1s[(b1r + 8) * 97 + ca] * v1s[(b1r + 8) * 97 + cv]);
#pragma unroll
        for (int ks = 0; ks < 7; ks++) {
            const uint32_t A0 = h2u(__hmul2(m0h, t1f[ks][0]));
            const uint32_t A1 = h2u(__hmul2(m1h, t1f[ks][1]));
            const uint32_t A2 = h2u(__hmul2(m0h, t1f[ks][2]));
            const uint32_t A3 = h2u(__hmul2(m1h, t1f[ks][3]));
            const uint32_t G0 = h2u(__hmul2(m2h, t1g[ks][0]));
            const uint32_t G1 = h2u(__hmul2(m3h, t1g[ks][1]));
            const uint32_t G2 = h2u(__hmul2(m2h, t1g[ks][2]));
            const uint32_t G3 = h2u(__hmul2(m3h, t1g[ks][3]));
            const __half* rowp = curb + (ks * 16 + lrow) * LDH + nbase;

            uint32_t s4 = (uint32_t)__cvta_generic_to_shared(rowp + lcol);
            uint32_t B0, B1, B2, B3;
            asm volatile(
                "ldmatrix.sync.aligned.m8n8.x4.trans.shared.b16 "
                "{%0,%1,%2,%3}, [%4];"
                : "=r"(B0), "=r"(B1), "=r"(B2), "=r"(B3) : "r"(s4));

            uint32_t s2 = (uint32_t)__cvta_generic_to_shared(rowp + 16);
            uint32_t C0, C1;
            asm volatile(
                "ldmatrix.sync.aligned.m8n8.x2.trans.shared.b16 "
                "{%0,%1}, [%2];"
                : "=r"(C0), "=r"(C1) : "r"(s2));

            mma_f16(Y[0], A0, A1, A2, A3, B0, B1);
            mma_f16(Y[1], A0, A1, A2, A3, B2, B3);
            mma_f16(Y[2], A0, A1, A2, A3, C0, C1);
            mma_f16(Y[3], G0, G1, G2, G3, B0, B1);
            mma_f16(Y[4], G0, G1, G2, G3, B2, B3);
            mma_f16(Y[5], G0, G1, G2, G3, C0, C1);
        }
    };

    // --- prefetch distance 3: 2 reg sets, 3 smem stages (R9-proven) ---
    float4 stgA[10], stgB[10];
    stage_ldg(stgA, W1, cstart, tid);                       // chunk 0
    if (ccnt > 1) stage_ldg(stgB, W1, cstart + 1, tid);     // chunk 1
    stage_sts(wb0, stgA, tid);                              // chunk 0 -> wb0
    if (ccnt > 2) stage_ldg(stgA, W1, cstart + 2, tid);     // chunk 2
    __syncthreads();

    __half *cur = wb0, *nxt = wb1, *spare = wb2;

    for (int ci = 0; ci < ccnt; ci += 2) {
        // even iter: compute chunk ci; stgB holds ci+1
        if (ci + 1 < ccnt) stage_sts(nxt, stgB, tid);
        if (ci + 3 < ccnt) stage_ldg(stgB, W1, cstart + ci + 3, tid);
        compute(cstart + ci, cur);
        __syncthreads();
        { __half* t = cur; cur = nxt; nxt = spare; spare = t; }

        // odd iter: compute chunk ci+1; stgA holds ci+2
        if (ci + 1 < ccnt) {
            if (ci + 2 < ccnt) stage_sts(nxt, stgA, tid);
            if (ci + 4 < ccnt) stage_ldg(stgA, W1, cstart + ci + 4, tid);
            compute(cstart + ci + 1, cur);
            __syncthreads();
            { __half* t = cur; cur = nxt; nxt = spare; spare = t; }
        }
    }

    // write fp32 partials [bk][b][h] (two m-tiles)
    float* dst = g_part + (size_t)bk * (BDIM * HDIM);
#pragma unroll
    for (int j = 0; j < 3; j++) {
        int h = nbase + 8 * j + 2 * tig;
        *reinterpret_cast<float2*>(dst + b0 * HDIM + h) =
            make_float2(Y[j][0], Y[j][1]);
        *reinterpret_cast<float2*>(dst + (b0 + 8) * HDIM + h) =
            make_float2(Y[j][2], Y[j][3]);
        *reinterpret_cast<float2*>(dst + b1r * HDIM + h) =
            make_float2(Y[3 + j][0], Y[3 + j][1]);
        *reinterpret_cast<float2*>(dst + (b1r + 8) * HDIM + h) =
            make_float2(Y[3 + j][2], Y[3 + j][3]);
    }
}

// ---------------------------------------------------------------------------
// Kernel 3: reduce partials + bias/relu + W2 + heads. One block per batch row.
// ---------------------------------------------------------------------------
__global__ void __launch_bounds__(768) tfn_tail(
    const float* __restrict__ b1, const float* __restrict__ W2,
    const float* __restrict__ b2,
    const float* __restrict__ Wo1, const float* __restrict__ bo1,
    const float* __restrict__ Wo2, const float* __restrict__ bo2,
    const float* __restrict__ Wo3, const float* __restrict__ bo3,
    float* __restrict__ out) {
    __shared__ float ps[768];
    __shared__ float yr[HDIM];
    __shared__ float fs[HDIM];
    const int b   = blockIdx.x;
    const int tid = threadIdx.x;
    const int h   = tid % 96;
    const int g   = tid / 96;   // 0..7

    float acc = 0.f;
#pragma unroll 4
    for (int p = g; p < NBLK; p += 8)
        acc += g_part[(size_t)p * (BDIM * HDIM) + b * HDIM + h];
    ps[tid] = acc;
    __syncthreads();

    if (g == 0) {
        float r = b1[h];
#pragma unroll
        for (int i = 0; i < 8; i++) r += ps[h + 96 * i];
        yr[h] = fmaxf(r, 0.f);
    }
    __syncthreads();

    if (g == 0) {
        float f = b2[h];
#pragma unroll 8
        for (int k = 0; k < HDIM; k++) f += yr[k] * W2[k * HDIM + h];
        f = fmaxf(f, 0.f);
        fs[h] = f;
        out[b * HDIM + h] = f;
    }
    __syncthreads();

    if (tid < 6) {
        float a = bo1[tid];
        for (int k = 0; k < HDIM; k++) a += fs[k] * Wo1[k * 6 + tid];
        out[6144 + b * 6 + tid] = a;
    } else if (tid == 6) {
        float a = bo2[0];
        for (int k = 0; k < HDIM; k++) a += fs[k] * Wo2[k];
        out[6528 + b] = a;
    } else if (tid < 10) {
        int o = tid - 7;
        float a = bo3[o];
        for (int k = 0; k < HDIM; k++) a += fs[k] * Wo3[k * 3 + o];
        out[6592 + b * 3 + o] = a;
    }
    if (b == 0 && tid == 95) out[6784] = 0.f;  // interloss
}

// ---------------------------------------------------------------------------

extern "C" void kernel_launch(void* const* d_in, const int* in_sizes, int n_in,
                              void* d_out, int out_size) {
    (void)in_sizes; (void)n_in; (void)out_size;
    const float* audios = (const float*)d_in[0];
    const float* texts  = (const float*)d_in[1];
    const float* videos = (const float*)d_in[2];
    const float* Wa  = (const float*)d_in[3];
    const float* ba  = (const float*)d_in[4];
    const float* Wt  = (const float*)d_in[5];
    const float* bt  = (const float*)d_in[6];
    const float* Wv  = (const float*)d_in[7];
    const float* bv  = (const float*)d_in[8];
    const float* W1  = (const float*)d_in[9];
    const float* b1  = (const float*)d_in[10];
    const float* W2  = (const float*)d_in[11];
    const float* b2  = (const float*)d_in[12];
    const float* Wo1 = (const float*)d_in[13];
    const float* bo1 = (const float*)d_in[14];
    const float* Wo2 = (const float*)d_in[15];
    const float* bo2 = (const float*)d_in[16];
    const float* Wo3 = (const float*)d_in[17];
    const float* bo3 = (const float*)d_in[18];
    float* out = (float*)d_out;

    cudaFuncSetAttribute(tfn_main, cudaFuncAttributeMaxDynamicSharedMemorySize,
                         SMEM_BYTES);

    tfn_enc<<<dim3(64, 3), 768>>>(audios, texts, videos, Wa, ba, Wt, bt, Wv, bv);
    tfn_main<<<NBLK, 256, SMEM_BYTES>>>(W1);
    tfn_tail<<<64, 768>>>(b1, W2, b2, Wo1, bo1, Wo2, bo2, Wo3, bo3, out);
}